// round 2
// baseline (speedup 1.0000x reference)
#include <cuda_runtime.h>
#include <cuda_bf16.h>
#include <math.h>

// ---------------- problem constants (fixed shapes) ----------------
#define M_ATOMS 8192
#define NB      16
#define NPG     512          // atoms per graph
#define FD      128          // feature dim
#define HD      64           // hidden
#define DD      16           // far source dim
#define SE      95           // shell feature dim (5*19)
#define EH      159          // energy head input dim
#define TABN    16384
#define INVD    118.0f       // table entries per unit distance (covers d<=138.8)
#define SPAD    20           // padded row (floats) for source tile

// ---------------- device scratch (no allocations allowed) ----------------
__device__ float d_tab[TABN + 1];
__device__ float d_srcraw[M_ATOMS * DD];   // LayerNorm'd source (pre-neutralization)
__device__ float d_gmean[NB * DD];         // per-graph mean of src
__device__ float d_shell[M_ATOMS * SE];    // shell features
__device__ float d_pa[M_ATOMS];            // per-atom energy

// ---------------- K0: kernel table:  f(d) = exp(-sigma d)/max(d,1e-6) * gate(d) ----------------
__global__ void table_kernel(const float* __restrict__ k_screen,
                             const float* __restrict__ kw1, const float* __restrict__ kb1,
                             const float* __restrict__ kw2, const float* __restrict__ kb2) {
    int i = blockIdx.x * blockDim.x + threadIdx.x;
    if (i > TABN) return;
    float d = (float)i / INVD;
    float scr = log1pf(expf(k_screen[0]));
    float base = expf(-scr * d) / fmaxf(d, 1e-6f);
    float g0 = d * (1.0f / 5.0f);
    float g1 = d * (1.0f / 40.0f);
    float rbf[8];
#pragma unroll
    for (int r = 0; r < 8; r++) {
        float dc = d - (5.0f + 5.0f * (float)r);
        rbf[r] = expf(-0.04f * dc * dc);   // gamma = 1/25
    }
    float out = kb2[0];
#pragma unroll 4
    for (int k = 0; k < 32; k++) {
        float a = kb1[k];
        a = fmaf(g0, kw1[0 * 32 + k], a);
        a = fmaf(g1, kw1[1 * 32 + k], a);
#pragma unroll
        for (int r = 0; r < 8; r++) a = fmaf(rbf[r], kw1[(2 + r) * 32 + k], a);
        float sl = a / (1.0f + expf(-a));   // silu
        out = fmaf(sl, kw2[k], out);
    }
    float gate = 1.0f + tanhf(out);
    d_tab[i] = base * gate;
}

// ---------------- K1: per-atom source features ----------------
__global__ __launch_bounds__(128) void src_kernel(
    const float* __restrict__ x,
    const float* __restrict__ ing, const float* __restrict__ inb,
    const float* __restrict__ w1, const float* __restrict__ b1,
    const float* __restrict__ w2, const float* __restrict__ b2,
    const float* __restrict__ lg, const float* __restrict__ lb) {
    int i = blockIdx.x;
    int t = threadIdx.x;
    __shared__ float sh[FD];
    __shared__ float rs[4], rq[4];
    __shared__ float hid2[2][HD];
    __shared__ float hid[HD];
    __shared__ float ob[DD];

    float v = x[(size_t)i * FD + t];
    float s = v, q = v * v;
#pragma unroll
    for (int o = 16; o; o >>= 1) {
        s += __shfl_xor_sync(0xffffffffu, s, o);
        q += __shfl_xor_sync(0xffffffffu, q, o);
    }
    if ((t & 31) == 0) { rs[t >> 5] = s; rq[t >> 5] = q; }
    __syncthreads();
    s = rs[0] + rs[1] + rs[2] + rs[3];
    q = rq[0] + rq[1] + rq[2] + rq[3];
    float mean = s * (1.0f / FD);
    float var  = q * (1.0f / FD) - mean * mean;
    float rstd = rsqrtf(var + 1e-5f);
    sh[t] = (v - mean) * rstd * ing[t] + inb[t];
    __syncthreads();

    {   // hidden layer: split 128 input dims across 2 halves of the block
        int k = t & 63, half = t >> 6;
        float a = 0.0f;
        int m0 = half * 64;
#pragma unroll 8
        for (int m = 0; m < 64; m++) a = fmaf(sh[m0 + m], w1[(m0 + m) * HD + k], a);
        hid2[half][k] = a;
    }
    __syncthreads();
    if (t < HD) {
        float u = hid2[0][t] + hid2[1][t] + b1[t];
        hid[t] = u / (1.0f + expf(-u));
    }
    __syncthreads();
    if (t < DD) {
        float a = b2[t];
#pragma unroll 8
        for (int k = 0; k < HD; k++) a = fmaf(hid[k], w2[k * DD + t], a);
        ob[t] = a;
        __syncwarp(0x0000ffffu);
        float s2 = 0.0f, q2 = 0.0f;
#pragma unroll
        for (int c = 0; c < DD; c++) { float u = ob[c]; s2 += u; q2 += u * u; }
        float mn = s2 * (1.0f / DD);
        float vr = q2 * (1.0f / DD) - mn * mn;
        float y = (a - mn) * rsqrtf(vr + 1e-5f) * lg[t] + lb[t];
        d_srcraw[(size_t)i * DD + t] = y;
    }
}

// ---------------- K2: per-graph mean of src ----------------
__global__ void mean_kernel() {
    int g = blockIdx.x;
    int t = threadIdx.x;          // 256 threads
    int c = t & 15, r0 = t >> 4;  // 16 row-lanes
    float a = 0.0f;
    for (int j = r0; j < NPG; j += 16)
        a += d_srcraw[(size_t)(g * NPG + j) * DD + c];
    __shared__ float sm[256];
    sm[t] = a;
    __syncthreads();
    if (t < DD) {
        float s = 0.0f;
#pragma unroll
        for (int k = 0; k < 16; k++) s += sm[k * 16 + t];
        d_gmean[g * DD + t] = s * (1.0f / NPG);
    }
}

// ---------------- K3: pairwise shell statistics ----------------
// 256 threads = 8 warps; 4 atoms per warp (8 j-lanes per atom) -> 32 atoms/block
#define GRED(v) { v += __shfl_down_sync(0xffffffffu, v, 4); \
                  v += __shfl_down_sync(0xffffffffu, v, 2); \
                  v += __shfl_down_sync(0xffffffffu, v, 1); }

__global__ __launch_bounds__(256) void pair_kernel(const float* __restrict__ pos) {
    __shared__ float sTf[NPG * SPAD];          // [j][20] padded, float4-readable
    __shared__ float px[NPG], py[NPG], pz[NPG];
    int g    = blockIdx.x >> 4;   // 16 blocks per graph
    int blk  = blockIdx.x & 15;   // 32 atoms per block
    int t    = threadIdx.x;
    int gbase = g * NPG;

    for (int idx = t; idx < NPG * DD; idx += 256) {
        int j = idx >> 4, c = idx & 15;
        sTf[j * SPAD + c] = d_srcraw[(size_t)(gbase + j) * DD + c] - __ldg(&d_gmean[g * DD + c]);
    }
    for (int j = t; j < NPG; j += 256) {
        const float* p = pos + (size_t)(gbase + j) * 3;
        px[j] = p[0]; py[j] = p[1]; pz[j] = p[2];
    }
    __syncthreads();

    int w = t >> 5, lane = t & 31;
    int a = lane >> 3, sub = lane & 7;
    int li = blk * 32 + w * 4 + a;          // local atom index
    float xi = px[li], yi = py[li], zi = pz[li];

    const float4* sT4 = (const float4*)sTf;  // row stride = 5 float4

    float am0[16], am1[16], am2[16], am3[16], am4[16];
    float ac[5], ad[5], ad2[5];
#pragma unroll
    for (int c = 0; c < 16; c++) { am0[c]=0.f; am1[c]=0.f; am2[c]=0.f; am3[c]=0.f; am4[c]=0.f; }
#pragma unroll
    for (int s = 0; s < 5; s++) { ac[s]=0.f; ad[s]=0.f; ad2[s]=0.f; }

#pragma unroll 4
    for (int it = 0; it < 64; it++) {
        int j = sub + it * 8;
        float dx = px[j] - xi, dy = py[j] - yi, dz = pz[j] - zi;
        float dsq = fmaf(dx, dx, fmaf(dy, dy, fmaf(dz, dz, 1e-12f)));
        float d = sqrtf(dsq);
        // table lookup (only consumed for d >= 5)
        float tt = d * INVD;
        int k = (int)tt; if (k > TABN - 1) k = TABN - 1;
        float fr = tt - (float)k;
        float v0 = __ldg(&d_tab[k]);
        float wv = fmaf(fr, __ldg(&d_tab[k + 1]) - v0, v0);
        // shell masks (self-pair d=1e-6 -> all masks zero)
        float m0 = (d >= 5.0f  && d < 10.0f) ? 1.0f : 0.0f;
        float m1 = (d >= 10.0f && d < 20.0f) ? 1.0f : 0.0f;
        float m2 = (d >= 20.0f && d < 40.0f) ? 1.0f : 0.0f;
        float m3 = (d >= 40.0f && d < 80.0f) ? 1.0f : 0.0f;
        float m4 = (d >= 80.0f) ? 1.0f : 0.0f;
        float w0 = wv * m0, w1 = wv * m1, w2 = wv * m2, w3 = wv * m3, w4 = wv * m4;
        float dd = d * d;
        ac[0] += m0; ad[0] = fmaf(m0, d, ad[0]); ad2[0] = fmaf(m0, dd, ad2[0]);
        ac[1] += m1; ad[1] = fmaf(m1, d, ad[1]); ad2[1] = fmaf(m1, dd, ad2[1]);
        ac[2] += m2; ad[2] = fmaf(m2, d, ad[2]); ad2[2] = fmaf(m2, dd, ad2[2]);
        ac[3] += m3; ad[3] = fmaf(m3, d, ad[3]); ad2[3] = fmaf(m3, dd, ad2[3]);
        ac[4] += m4; ad[4] = fmaf(m4, d, ad[4]); ad2[4] = fmaf(m4, dd, ad2[4]);
        float4 s0 = sT4[j * 5 + 0];
        float4 s1 = sT4[j * 5 + 1];
        float4 s2 = sT4[j * 5 + 2];
        float4 s3 = sT4[j * 5 + 3];
        float sv[16] = { s0.x, s0.y, s0.z, s0.w, s1.x, s1.y, s1.z, s1.w,
                         s2.x, s2.y, s2.z, s2.w, s3.x, s3.y, s3.z, s3.w };
#pragma unroll
        for (int c = 0; c < 16; c++) {
            am0[c] = fmaf(w0, sv[c], am0[c]);
            am1[c] = fmaf(w1, sv[c], am1[c]);
            am2[c] = fmaf(w2, sv[c], am2[c]);
            am3[c] = fmaf(w3, sv[c], am3[c]);
            am4[c] = fmaf(w4, sv[c], am4[c]);
        }
    }

    // reduce within each 8-lane group
#pragma unroll
    for (int s = 0; s < 5; s++) { GRED(ac[s]); GRED(ad[s]); GRED(ad2[s]); }
#pragma unroll
    for (int c = 0; c < 16; c++) { GRED(am0[c]); GRED(am1[c]); GRED(am2[c]); GRED(am3[c]); GRED(am4[c]); }

    if (sub == 0) {
        int i = gbase + li;
        float* o = d_shell + (size_t)i * SE;
        float den, cnt;
        cnt = ac[0]; den = fmaxf(cnt, 1.0f);
#pragma unroll
        for (int c = 0; c < 16; c++) o[0*19 + c] = am0[c] / den;
        o[0*19+16] = cnt; o[0*19+17] = ad[0] / den; o[0*19+18] = sqrtf(ad2[0] / den + 1e-12f);
        cnt = ac[1]; den = fmaxf(cnt, 1.0f);
#pragma unroll
        for (int c = 0; c < 16; c++) o[1*19 + c] = am1[c] / den;
        o[1*19+16] = cnt; o[1*19+17] = ad[1] / den; o[1*19+18] = sqrtf(ad2[1] / den + 1e-12f);
        cnt = ac[2]; den = fmaxf(cnt, 1.0f);
#pragma unroll
        for (int c = 0; c < 16; c++) o[2*19 + c] = am2[c] / den;
        o[2*19+16] = cnt; o[2*19+17] = ad[2] / den; o[2*19+18] = sqrtf(ad2[2] / den + 1e-12f);
        cnt = ac[3]; den = fmaxf(cnt, 1.0f);
#pragma unroll
        for (int c = 0; c < 16; c++) o[3*19 + c] = am3[c] / den;
        o[3*19+16] = cnt; o[3*19+17] = ad[3] / den; o[3*19+18] = sqrtf(ad2[3] / den + 1e-12f);
        cnt = ac[4]; den = fmaxf(cnt, 1.0f);
#pragma unroll
        for (int c = 0; c < 16; c++) o[4*19 + c] = am4[c] / den;
        o[4*19+16] = cnt; o[4*19+17] = ad[4] / den; o[4*19+18] = sqrtf(ad2[4] / den + 1e-12f);
    }
}

// ---------------- K4: per-atom energy head ----------------
__global__ __launch_bounds__(64) void energy_kernel(
    const float* __restrict__ seg, const float* __restrict__ seb,
    const float* __restrict__ sw1, const float* __restrict__ sb1,
    const float* __restrict__ sw2, const float* __restrict__ sb2,
    const float* __restrict__ eg,  const float* __restrict__ ebv,
    const float* __restrict__ ew1, const float* __restrict__ eb1,
    const float* __restrict__ ew2, const float* __restrict__ eb2,
    const float* __restrict__ far_gate, const float* __restrict__ escale) {
    int i = blockIdx.x;
    int t = threadIdx.x;   // 64
    int g = i >> 9;
    __shared__ float shell[SE];
    __shared__ float buf[EH];
    __shared__ float nb[EH];
    __shared__ float hid[HD];
    __shared__ float srcc[DD];
    __shared__ float embs[DD];
    __shared__ float rs[2], rq[2], pr[2];

    for (int idx = t; idx < SE; idx += 64) shell[idx] = d_shell[(size_t)i * SE + idx];
    if (t < DD) srcc[t] = d_srcraw[(size_t)i * DD + t] - d_gmean[g * DD + t];
    __syncthreads();

    // LayerNorm(shell, 95)
    float s = 0.0f, q = 0.0f;
    for (int idx = t; idx < SE; idx += 64) { float v = shell[idx]; s += v; q += v * v; }
#pragma unroll
    for (int o = 16; o; o >>= 1) {
        s += __shfl_xor_sync(0xffffffffu, s, o);
        q += __shfl_xor_sync(0xffffffffu, q, o);
    }
    if ((t & 31) == 0) { rs[t >> 5] = s; rq[t >> 5] = q; }
    __syncthreads();
    s = rs[0] + rs[1]; q = rq[0] + rq[1];
    {
        float mn = s * (1.0f / SE);
        float vr = q * (1.0f / SE) - mn * mn;
        float rstd = rsqrtf(vr + 1e-5f);
        for (int idx = t; idx < SE; idx += 64)
            nb[idx] = (shell[idx] - mn) * rstd * seg[idx] + seb[idx];
    }
    __syncthreads();

    {   // se MLP hidden
        float a2 = sb1[t];
#pragma unroll 5
        for (int m = 0; m < SE; m++) a2 = fmaf(nb[m], sw1[m * HD + t], a2);
        hid[t] = a2 / (1.0f + expf(-a2));
    }
    __syncthreads();
    if (t < DD) {
        float e = sb2[t];
#pragma unroll 8
        for (int k = 0; k < HD; k++) e = fmaf(hid[k], sw2[k * DD + t], e);
        embs[t] = e;
    }
    __syncthreads();

    // build ein = [src, emb, src*emb, src-emb, shell]
    if (t < DD) {
        float sc = srcc[t], e = embs[t];
        buf[t] = sc; buf[16 + t] = e; buf[32 + t] = sc * e; buf[48 + t] = sc - e;
    }
    for (int idx = t; idx < SE; idx += 64) buf[64 + idx] = shell[idx];
    __syncthreads();

    // LayerNorm(ein, 159)
    s = 0.0f; q = 0.0f;
    for (int idx = t; idx < EH; idx += 64) { float v = buf[idx]; s += v; q += v * v; }
#pragma unroll
    for (int o = 16; o; o >>= 1) {
        s += __shfl_xor_sync(0xffffffffu, s, o);
        q += __shfl_xor_sync(0xffffffffu, q, o);
    }
    if ((t & 31) == 0) { rs[t >> 5] = s; rq[t >> 5] = q; }
    __syncthreads();
    s = rs[0] + rs[1]; q = rq[0] + rq[1];
    {
        float mn = s * (1.0f / EH);
        float vr = q * (1.0f / EH) - mn * mn;
        float rstd = rsqrtf(vr + 1e-5f);
        for (int idx = t; idx < EH; idx += 64)
            nb[idx] = (buf[idx] - mn) * rstd * eg[idx] + ebv[idx];
    }
    __syncthreads();

    {   // eh MLP hidden + output
        float a2 = eb1[t];
#pragma unroll 3
        for (int m = 0; m < EH; m++) a2 = fmaf(nb[m], ew1[m * HD + t], a2);
        a2 = a2 / (1.0f + expf(-a2));
        float part = a2 * ew2[t];
#pragma unroll
        for (int o = 16; o; o >>= 1) part += __shfl_xor_sync(0xffffffffu, part, o);
        if ((t & 31) == 0) pr[t >> 5] = part;
    }
    __syncthreads();
    if (t == 0) {
        float pa = pr[0] + pr[1] + eb2[0];
        pa *= tanhf(far_gate[0]) * expf(escale[0]);
        d_pa[i] = pa;
    }
}

// ---------------- K5: per-graph energy sum (deterministic, double acc) ----------------
__global__ __launch_bounds__(512) void reduce_kernel(float* __restrict__ out) {
    int g = blockIdx.x;
    int t = threadIdx.x;   // 512
    double v = (double)d_pa[g * NPG + t];
#pragma unroll
    for (int o = 16; o; o >>= 1) v += __shfl_xor_sync(0xffffffffu, v, o);
    __shared__ double sd[16];
    if ((t & 31) == 0) sd[t >> 5] = v;
    __syncthreads();
    if (t == 0) {
        double s = 0.0;
#pragma unroll
        for (int k = 0; k < 16; k++) s += sd[k];
        out[g] = (float)s;
    }
}

// ---------------- launcher (self-locating input map) ----------------
extern "C" void kernel_launch(void* const* d_in, const int* in_sizes, int n_in,
                              void* d_out, int out_size) {
    const float* x   = (const float*)d_in[0];
    const float* pos = (const float*)d_in[1];
    // d_in[2] = batch (int32). After it there MAY be a size-1 num_graphs entry.
    int idx = 3;
    if (idx < n_in && in_sizes[idx] == 1 && in_sizes[idx + 1] == FD) idx++;  // skip num_graphs scalar

    const float* in_ln_g = (const float*)d_in[idx++];
    const float* in_ln_b = (const float*)d_in[idx++];
    const float* src_w1  = (const float*)d_in[idx++];
    const float* src_b1  = (const float*)d_in[idx++];
    const float* src_w2  = (const float*)d_in[idx++];
    const float* src_b2  = (const float*)d_in[idx++];
    const float* src_lng = (const float*)d_in[idx++];
    const float* src_lnb = (const float*)d_in[idx++];
    const float* se_ln_g = (const float*)d_in[idx++];
    const float* se_ln_b = (const float*)d_in[idx++];
    const float* se_w1   = (const float*)d_in[idx++];
    const float* se_b1   = (const float*)d_in[idx++];
    const float* se_w2   = (const float*)d_in[idx++];
    const float* se_b2   = (const float*)d_in[idx++];
    const float* eh_ln_g = (const float*)d_in[idx++];
    const float* eh_ln_b = (const float*)d_in[idx++];
    const float* eh_w1   = (const float*)d_in[idx++];
    const float* eh_b1   = (const float*)d_in[idx++];
    const float* eh_w2   = (const float*)d_in[idx++];
    const float* eh_b2   = (const float*)d_in[idx++];
    const float* k_scr   = (const float*)d_in[idx++];
    const float* kg_w1   = (const float*)d_in[idx++];
    const float* kg_b1   = (const float*)d_in[idx++];
    const float* kg_w2   = (const float*)d_in[idx++];
    const float* kg_b2   = (const float*)d_in[idx++];
    const float* far_g   = (const float*)d_in[idx++];
    const float* e_scale = (const float*)d_in[idx++];

    table_kernel<<<(TABN + 256) / 256, 256>>>(k_scr, kg_w1, kg_b1, kg_w2, kg_b2);
    src_kernel<<<M_ATOMS, 128>>>(x, in_ln_g, in_ln_b, src_w1, src_b1, src_w2, src_b2, src_lng, src_lnb);
    mean_kernel<<<NB, 256>>>();
    pair_kernel<<<NB * 16, 256>>>(pos);
    energy_kernel<<<M_ATOMS, 64>>>(se_ln_g, se_ln_b, se_w1, se_b1, se_w2, se_b2,
                                   eh_ln_g, eh_ln_b, eh_w1, eh_b1, eh_w2, eh_b2,
                                   far_g, e_scale);
    reduce_kernel<<<NB, 512>>>((float*)d_out);
}